// round 1
// baseline (speedup 1.0000x reference)
#include <cuda_runtime.h>
#include <cstdint>

// TitansMemoryModule fused kernel (tf32 mma.sync path)
// inputs: k (N,64) f32 | v (N,64) f32 | W (64,64) f32 | gate_w (3,64) f32 |
//         gate_b (3) f32 | momentum_S (64,64) f32
// output (f32): retrieved (N*64) | loss (1) | new_W (4096) | new_S (4096) | gates (3)

#define TILE   128
#define PITCH  68          // 64 + 4 pad: conflict-free strided fragment access
#define D      64

static constexpr int SMEM_FLOATS = TILE * PITCH * 2 + D * PITCH;   // k_sh + d_sh + w_sh
static constexpr int SMEM_BYTES  = SMEM_FLOATS * 4;                // 87040

__device__ float g_gradAcc[D * D];
__device__ float g_ksum[D];
__device__ float g_loss;

__device__ __forceinline__ float tf32r(float x) {
    uint32_t u;
    asm("cvt.rna.tf32.f32 %0, %1;" : "=r"(u) : "f"(x));
    return __uint_as_float(u);
}

__device__ __forceinline__ void mma8(float* c,
                                     uint32_t a0, uint32_t a1, uint32_t a2, uint32_t a3,
                                     uint32_t b0, uint32_t b1) {
    asm volatile(
        "mma.sync.aligned.m16n8k8.row.col.f32.tf32.tf32.f32 "
        "{%0,%1,%2,%3}, {%4,%5,%6,%7}, {%8,%9}, {%0,%1,%2,%3};"
        : "+f"(c[0]), "+f"(c[1]), "+f"(c[2]), "+f"(c[3])
        : "r"(a0), "r"(a1), "r"(a2), "r"(a3), "r"(b0), "r"(b1));
}

__global__ void zero_scratch_kernel() {
    int t = blockIdx.x * blockDim.x + threadIdx.x;
    if (t < D * D) g_gradAcc[t] = 0.0f;
    if (t < D)     g_ksum[t]    = 0.0f;
    if (t == 0)    g_loss       = 0.0f;
}

__global__ __launch_bounds__(256, 2)
void titans_main_kernel(const float* __restrict__ kmat,
                        const float* __restrict__ vmat,
                        const float* __restrict__ W,
                        float* __restrict__ ret,
                        int N) {
    extern __shared__ float sh[];
    float* k_sh = sh;                      // TILE x PITCH (tf32-rounded)
    float* d_sh = sh + TILE * PITCH;       // TILE x PITCH (tf32-rounded diff)
    float* w_sh = d_sh + TILE * PITCH;     // D x PITCH    (tf32-rounded W)

    const int tid  = threadIdx.x;
    const int lane = tid & 31;
    const int warp = tid >> 5;             // 0..7
    const int lp   = lane >> 2;            // 0..7 (group)
    const int lq   = lane & 3;             // 0..3 (thread-in-group)

    // stage W (row j, col d) once, tf32-rounded
    for (int i = tid; i < D * D; i += 256) {
        w_sh[(i >> 6) * PITCH + (i & 63)] = tf32r(W[i]);
    }

    // persistent grad accumulators: warp stripe j in [jbase, jbase+16), K-half kbase
    const int jbase = (warp & 3) * 16;
    const int kbase = (warp >> 2) * 64;
    float gacc[8][4];
#pragma unroll
    for (int n = 0; n < 8; n++)
#pragma unroll
        for (int i = 0; i < 4; i++) gacc[n][i] = 0.0f;

    float loss_local = 0.0f;
    float ks_local   = 0.0f;
    const int kscol  = tid & 63;
    const int ksrow0 = (tid >> 6) * 32;

    const int ntiles = N / TILE;
    const int row0   = warp * 16;

    for (int tile = blockIdx.x; tile < ntiles; tile += gridDim.x) {
        __syncthreads();   // previous GEMM2 done reading k_sh / d_sh

        // ---- stage k tile (tf32) ----
        const float* kt = kmat + (size_t)tile * TILE * D;
#pragma unroll
        for (int it = 0; it < 8; it++) {
            int i = tid + it * 256;        // float4 index in [0, 2048)
            int r = i >> 4, q = i & 15;
            float4 x = reinterpret_cast<const float4*>(kt)[i];
            x.x = tf32r(x.x); x.y = tf32r(x.y); x.z = tf32r(x.z); x.w = tf32r(x.w);
            *reinterpret_cast<float4*>(&k_sh[r * PITCH + q * 4]) = x;
        }
        __syncthreads();

        // ---- column sums of k (for mean-key gates) ----
#pragma unroll
        for (int r = 0; r < 32; r++)
            ks_local += k_sh[(ksrow0 + r) * PITCH + kscol];

        // ---- GEMM1: C(16x64) = k_rows(16x64) @ W^T ----
        float c1[8][4];
#pragma unroll
        for (int n = 0; n < 8; n++)
#pragma unroll
            for (int i = 0; i < 4; i++) c1[n][i] = 0.0f;

#pragma unroll
        for (int kk = 0; kk < 8; kk++) {
            const int kc = kk * 8;
            uint32_t a0 = __float_as_uint(k_sh[(row0 + lp) * PITCH + kc + lq]);
            uint32_t a1 = __float_as_uint(k_sh[(row0 + lp + 8) * PITCH + kc + lq]);
            uint32_t a2 = __float_as_uint(k_sh[(row0 + lp) * PITCH + kc + lq + 4]);
            uint32_t a3 = __float_as_uint(k_sh[(row0 + lp + 8) * PITCH + kc + lq + 4]);
#pragma unroll
            for (int n = 0; n < 8; n++) {
                uint32_t b0 = __float_as_uint(w_sh[(n * 8 + lp) * PITCH + kc + lq]);
                uint32_t b1 = __float_as_uint(w_sh[(n * 8 + lp) * PITCH + kc + lq + 4]);
                mma8(c1[n], a0, a1, a2, a3, b0, b1);
            }
        }

        // ---- epilogue: diff, retrieved store, loss, stage diff (tf32) ----
        const size_t gr0 = (size_t)(tile * TILE + row0 + lp) * D;
        const int    lr  = row0 + lp;
#pragma unroll
        for (int n = 0; n < 8; n++) {
            const int col = n * 8 + 2 * lq;
            float2 va = *reinterpret_cast<const float2*>(&vmat[gr0 + col]);
            float2 vb = *reinterpret_cast<const float2*>(&vmat[gr0 + 8 * D + col]);
            float d0 = c1[n][0] - va.x;
            float d1 = c1[n][1] - va.y;
            float d2 = c1[n][2] - vb.x;
            float d3 = c1[n][3] - vb.y;
            float2 r01 = make_float2(c1[n][0], c1[n][1]);
            float2 r23 = make_float2(c1[n][2], c1[n][3]);
            *reinterpret_cast<float2*>(&ret[gr0 + col])         = r01;
            *reinterpret_cast<float2*>(&ret[gr0 + 8 * D + col]) = r23;
            loss_local += d0 * d0 + d1 * d1 + d2 * d2 + d3 * d3;
            d_sh[lr * PITCH + col]           = tf32r(d0);
            d_sh[lr * PITCH + col + 1]       = tf32r(d1);
            d_sh[(lr + 8) * PITCH + col]     = tf32r(d2);
            d_sh[(lr + 8) * PITCH + col + 1] = tf32r(d3);
        }
        __syncthreads();

        // ---- GEMM2: gacc(16x64) += diff^T(jbase stripe, K=64 half) @ k_tile ----
#pragma unroll
        for (int kk = 0; kk < 8; kk++) {
            const int krow = kbase + kk * 8;
            uint32_t a0 = __float_as_uint(d_sh[(krow + lq) * PITCH + jbase + lp]);
            uint32_t a1 = __float_as_uint(d_sh[(krow + lq) * PITCH + jbase + lp + 8]);
            uint32_t a2 = __float_as_uint(d_sh[(krow + lq + 4) * PITCH + jbase + lp]);
            uint32_t a3 = __float_as_uint(d_sh[(krow + lq + 4) * PITCH + jbase + lp + 8]);
#pragma unroll
            for (int n = 0; n < 8; n++) {
                uint32_t b0 = __float_as_uint(k_sh[(krow + lq) * PITCH + n * 8 + lp]);
                uint32_t b1 = __float_as_uint(k_sh[(krow + lq + 4) * PITCH + n * 8 + lp]);
                mma8(gacc[n], a0, a1, a2, a3, b0, b1);
            }
        }
    }

    // ---- global accumulation ----
    // grad fragments -> g_gradAcc  (C row = j, col = d)
#pragma unroll
    for (int n = 0; n < 8; n++) {
        const int col = n * 8 + 2 * lq;
        const int r0i = (jbase + lp) * D;
        const int r1i = (jbase + lp + 8) * D;
        atomicAdd(&g_gradAcc[r0i + col],     gacc[n][0]);
        atomicAdd(&g_gradAcc[r0i + col + 1], gacc[n][1]);
        atomicAdd(&g_gradAcc[r1i + col],     gacc[n][2]);
        atomicAdd(&g_gradAcc[r1i + col + 1], gacc[n][3]);
    }
    atomicAdd(&g_ksum[kscol], ks_local);

    // block-reduce loss, then one atomic per block
    __syncthreads();
    sh[tid] = loss_local;
    __syncthreads();
#pragma unroll
    for (int s = 128; s > 0; s >>= 1) {
        if (tid < s) sh[tid] += sh[tid + s];
        __syncthreads();
    }
    if (tid == 0) atomicAdd(&g_loss, sh[0]);
}

__global__ void titans_final_kernel(const float* __restrict__ W,
                                    const float* __restrict__ gate_w,
                                    const float* __restrict__ gate_b,
                                    const float* __restrict__ S,
                                    float* __restrict__ out,
                                    int N) {
    __shared__ float gates_sh[3];
    __shared__ float red[256];
    __shared__ float scale_sh;
    const int tid = threadIdx.x;
    const float numel = (float)N * (float)D;

    const size_t loss_off = (size_t)N * D;
    const size_t nw_off   = loss_off + 1;
    const size_t ns_off   = nw_off + D * D;
    const size_t g_off    = ns_off + D * D;

    if (tid == 0) {
        float invN = 1.0f / (float)N;
        for (int i = 0; i < 3; i++) {
            float s = gate_b[i];
            for (int d = 0; d < D; d++) s += gate_w[i * D + d] * (g_ksum[d] * invN);
            gates_sh[i] = 1.0f / (1.0f + __expf(-s));
        }
        out[loss_off] = g_loss / numel;
    }
    __syncthreads();
    const float alpha = gates_sh[0];
    const float eta   = gates_sh[1];
    const float theta = gates_sh[2];

    float wlocal[16];
    float ss = 0.0f;
#pragma unroll
    for (int i = 0; i < 16; i++) {
        int idx = tid * 16 + i;
        float g = g_gradAcc[idx] * (2.0f / numel);
        g = fminf(1.0f, fmaxf(-1.0f, g));
        float ns = eta * S[idx] - 0.01f * theta * g;
        float nw = (1.0f - alpha) * W[idx] + ns;
        out[ns_off + idx] = ns;
        wlocal[i] = nw;
        ss += nw * nw;
    }
    red[tid] = ss;
    __syncthreads();
#pragma unroll
    for (int s = 128; s > 0; s >>= 1) {
        if (tid < s) red[tid] += red[tid + s];
        __syncthreads();
    }
    if (tid == 0) {
        float wnorm = sqrtf(red[0]);
        scale_sh = (wnorm > 10.0f) ? (10.0f / (wnorm + 1e-8f)) : 1.0f;
    }
    __syncthreads();
    const float sc = scale_sh;
#pragma unroll
    for (int i = 0; i < 16; i++) {
        int idx = tid * 16 + i;
        out[nw_off + idx] = wlocal[i] * sc;
    }
    if (tid < 3) out[g_off + tid] = gates_sh[tid];
}

extern "C" void kernel_launch(void* const* d_in, const int* in_sizes, int n_in,
                              void* d_out, int out_size) {
    const float* k  = (const float*)d_in[0];
    const float* v  = (const float*)d_in[1];
    const float* W  = (const float*)d_in[2];
    const float* gw = (const float*)d_in[3];
    const float* gb = (const float*)d_in[4];
    const float* S  = (const float*)d_in[5];
    float* out = (float*)d_out;

    const int N = in_sizes[0] / D;

    cudaFuncSetAttribute(titans_main_kernel,
                         cudaFuncAttributeMaxDynamicSharedMemorySize, SMEM_BYTES);

    zero_scratch_kernel<<<16, 256>>>();
    titans_main_kernel<<<304, 256, SMEM_BYTES>>>(k, v, W, out, N);
    titans_final_kernel<<<1, 256>>>(W, gw, gb, S, out, N);
}

// round 2
// speedup vs baseline: 1.0750x; 1.0750x over previous
#include <cuda_runtime.h>
#include <cuda_fp16.h>
#include <cstdint>

// TitansMemoryModule fused kernel — fp16 mma.sync (m16n8k16) + double-buffered pipeline
// inputs: k (N,64) f32 | v (N,64) f32 | W (64,64) f32 | gate_w (3,64) f32 |
//         gate_b (3) f32 | momentum_S (64,64) f32
// output (f32): retrieved (N*64) | loss (1) | new_W (4096) | new_S (4096) | gates (3)

#define TILE 128
#define PH   72            // smem pitch in halves: 144B rows => conflict-free ldmatrix
#define D    64

static constexpr int KBUF = TILE * PH;                 // 9216 halves
static constexpr int SMEM_HALVES = 4 * KBUF + D * PH;  // 2x kbuf + 2x dbuf + w
static constexpr int SMEM_BYTES  = SMEM_HALVES * 2;    // 82944 B -> 2 CTAs/SM

__device__ float g_gradAcc[D * D];
__device__ float g_ksum[D];
__device__ float g_loss;

__device__ __forceinline__ uint32_t sh_u32(const void* p) {
    return (uint32_t)__cvta_generic_to_shared(p);
}
__device__ __forceinline__ void ldsm4(uint32_t& r0, uint32_t& r1, uint32_t& r2, uint32_t& r3, uint32_t a) {
    asm volatile("ldmatrix.sync.aligned.m8n8.x4.shared.b16 {%0,%1,%2,%3},[%4];"
                 : "=r"(r0), "=r"(r1), "=r"(r2), "=r"(r3) : "r"(a));
}
__device__ __forceinline__ void ldsm4t(uint32_t& r0, uint32_t& r1, uint32_t& r2, uint32_t& r3, uint32_t a) {
    asm volatile("ldmatrix.sync.aligned.m8n8.x4.trans.shared.b16 {%0,%1,%2,%3},[%4];"
                 : "=r"(r0), "=r"(r1), "=r"(r2), "=r"(r3) : "r"(a));
}
__device__ __forceinline__ void mma16(float* c,
                                      uint32_t a0, uint32_t a1, uint32_t a2, uint32_t a3,
                                      uint32_t b0, uint32_t b1) {
    asm volatile("mma.sync.aligned.m16n8k16.row.col.f32.f16.f16.f32 "
                 "{%0,%1,%2,%3},{%4,%5,%6,%7},{%8,%9},{%0,%1,%2,%3};"
                 : "+f"(c[0]), "+f"(c[1]), "+f"(c[2]), "+f"(c[3])
                 : "r"(a0), "r"(a1), "r"(a2), "r"(a3), "r"(b0), "r"(b1));
}

__global__ void zero_scratch_kernel() {
    int t = blockIdx.x * blockDim.x + threadIdx.x;
    if (t < D * D) g_gradAcc[t] = 0.0f;
    if (t < D)     g_ksum[t]    = 0.0f;
    if (t == 0)    g_loss       = 0.0f;
}

__global__ __launch_bounds__(256, 2)
void titans_main_kernel(const float* __restrict__ kmat,
                        const float* __restrict__ vmat,
                        const float* __restrict__ W,
                        float* __restrict__ ret,
                        int N) {
    extern __shared__ __half sh[];
    __half* kb0 = sh;
    __half* kb1 = sh + KBUF;
    __half* db0 = sh + 2 * KBUF;
    __half* db1 = sh + 3 * KBUF;
    __half* wsh = sh + 4 * KBUF;

    const int tid  = threadIdx.x;
    const int lane = tid & 31;
    const int warp = tid >> 5;         // 0..7
    const int lp   = lane >> 2;
    const int lq   = lane & 3;
    const int row0 = warp * 16;                 // GEMM1 row stripe
    const int jbase = (warp & 3) * 16;          // GEMM2 j stripe
    const int shalf = (warp >> 2) * 64;         // GEMM2 sample half

    // stage W as fp16 once
    for (int i = tid; i < D * D; i += 256)
        wsh[(i >> 6) * PH + (i & 63)] = __float2half(W[i]);

    const int qcol = (tid & 15) * 4;   // this thread's fixed staging columns

    float ks4[4] = {0.f, 0.f, 0.f, 0.f};
    float gacc[8][4];
#pragma unroll
    for (int n = 0; n < 8; n++)
#pragma unroll
        for (int i = 0; i < 4; i++) gacc[n][i] = 0.0f;
    float loss_local = 0.0f;

    const int grid   = gridDim.x;
    const int ntiles = N / TILE;

    // ---- prologue: stage first tile into kb0 ----
    {
        const float* kt = kmat + (size_t)blockIdx.x * TILE * D;
#pragma unroll
        for (int it = 0; it < 8; it++) {
            int i = tid + it * 256;
            int r = i >> 4;
            float4 x = reinterpret_cast<const float4*>(kt)[i];
            ks4[0] += x.x; ks4[1] += x.y; ks4[2] += x.z; ks4[3] += x.w;
            *reinterpret_cast<__half2*>(&kb0[r * PH + qcol])     = __floats2half2_rn(x.x, x.y);
            *reinterpret_cast<__half2*>(&kb0[r * PH + qcol + 2]) = __floats2half2_rn(x.z, x.w);
        }
    }

    int p = 0;
    for (int tile = blockIdx.x; tile < ntiles; tile += grid, p ^= 1) {
        const __half* ks = p ? kb1 : kb0;
        __half*       ds = p ? db1 : db0;
        __half*       kn = p ? kb0 : kb1;

        const size_t gr0 = (size_t)(tile * TILE + row0 + lp) * D;

        // prefetch v (upper 8 rows) — consumed after GEMM1
        float2 va[8];
#pragma unroll
        for (int n = 0; n < 8; n++)
            va[n] = *reinterpret_cast<const float2*>(&vmat[gr0 + n * 8 + 2 * lq]);

        __syncthreads();   // kb[p] staged; db[p] free (last read 2 iters ago)

        // ---- GEMM1: C(16x64) = k_tile_rows @ W^T ----
        float c1[8][4];
#pragma unroll
        for (int n = 0; n < 8; n++)
#pragma unroll
            for (int i = 0; i < 4; i++) c1[n][i] = 0.0f;

#pragma unroll
        for (int kk = 0; kk < 4; kk++) {
            const int kbs = kk * 16;
            uint32_t a0, a1, a2, a3;
            ldsm4(a0, a1, a2, a3,
                  sh_u32(&ks[(row0 + (lane & 15)) * PH + kbs + ((lane >> 4) << 3)]));
#pragma unroll
            for (int j = 0; j < 4; j++) {
                const int bt = (2 * j + (lane >> 4)) * 8 + (lane & 7);
                const int bc = kbs + ((lane >> 3) & 1) * 8;
                uint32_t b0, b1, b2, b3;
                ldsm4(b0, b1, b2, b3, sh_u32(&wsh[bt * PH + bc]));
                mma16(c1[2 * j],     a0, a1, a2, a3, b0, b1);
                mma16(c1[2 * j + 1], a0, a1, a2, a3, b2, b3);
            }
        }

        // ---- epilogue: v(lower), diff, ret store, loss, stage diff fp16 ----
        float2 vb[8];
#pragma unroll
        for (int n = 0; n < 8; n++)
            vb[n] = *reinterpret_cast<const float2*>(&vmat[gr0 + 8 * D + n * 8 + 2 * lq]);

        const int lr = row0 + lp;
#pragma unroll
        for (int n = 0; n < 8; n++) {
            const int col = n * 8 + 2 * lq;
            float d0 = c1[n][0] - va[n].x;
            float d1 = c1[n][1] - va[n].y;
            float d2 = c1[n][2] - vb[n].x;
            float d3 = c1[n][3] - vb[n].y;
            *reinterpret_cast<float2*>(&ret[gr0 + col])         = make_float2(c1[n][0], c1[n][1]);
            *reinterpret_cast<float2*>(&ret[gr0 + 8 * D + col]) = make_float2(c1[n][2], c1[n][3]);
            loss_local += d0 * d0 + d1 * d1 + d2 * d2 + d3 * d3;
            *reinterpret_cast<__half2*>(&ds[lr * PH + col])       = __floats2half2_rn(d0, d1);
            *reinterpret_cast<__half2*>(&ds[(lr + 8) * PH + col]) = __floats2half2_rn(d2, d3);
        }

        // prefetch next k tile into registers (latency hidden by GEMM2)
        const int tnext = tile + grid;
        const bool have = tnext < ntiles;
        float4 kpre[8];
        {
            const float* kt = kmat + (size_t)tnext * TILE * D;
#pragma unroll
            for (int it = 0; it < 8; it++) {
                int i = tid + it * 256;
                kpre[it] = have ? reinterpret_cast<const float4*>(kt)[i]
                                : make_float4(0.f, 0.f, 0.f, 0.f);
            }
        }

        __syncthreads();   // db[p] complete

        // ---- GEMM2: gacc(16j x 64d) += diff^T @ k  (ldmatrix.trans operands) ----
#pragma unroll
        for (int kk = 0; kk < 4; kk++) {
            const int sb = shalf + kk * 16;
            uint32_t a0, a1, a2, a3;
            ldsm4t(a0, a1, a2, a3,
                   sh_u32(&ds[(sb + ((lane >> 4) << 3) + (lane & 7)) * PH
                              + jbase + ((lane >> 3) & 1) * 8]));
#pragma unroll
            for (int j = 0; j < 4; j++) {
                const int srow = sb + ((lane >> 3) & 1) * 8 + (lane & 7);
                const int dcol = (2 * j + (lane >> 4)) * 8;
                uint32_t b0, b1, b2, b3;
                ldsm4t(b0, b1, b2, b3, sh_u32(&ks[srow * PH + dcol]));
                mma16(gacc[2 * j],     a0, a1, a2, a3, b0, b1);
                mma16(gacc[2 * j + 1], a0, a1, a2, a3, b2, b3);
            }
        }

        // ---- stage prefetched k into the other buffer ----
        if (have) {
#pragma unroll
            for (int it = 0; it < 8; it++) {
                int r = (tid + it * 256) >> 4;
                float4 x = kpre[it];
                ks4[0] += x.x; ks4[1] += x.y; ks4[2] += x.z; ks4[3] += x.w;
                *reinterpret_cast<__half2*>(&kn[r * PH + qcol])     = __floats2half2_rn(x.x, x.y);
                *reinterpret_cast<__half2*>(&kn[r * PH + qcol + 2]) = __floats2half2_rn(x.z, x.w);
            }
        }
    }

    // ---- global accumulation ----
#pragma unroll
    for (int n = 0; n < 8; n++) {
        const int col = n * 8 + 2 * lq;
        const int r0i = (jbase + lp) * D;
        const int r1i = (jbase + lp + 8) * D;
        atomicAdd(&g_gradAcc[r0i + col],     gacc[n][0]);
        atomicAdd(&g_gradAcc[r0i + col + 1], gacc[n][1]);
        atomicAdd(&g_gradAcc[r1i + col],     gacc[n][2]);
        atomicAdd(&g_gradAcc[r1i + col + 1], gacc[n][3]);
    }
#pragma unroll
    for (int c = 0; c < 4; c++)
        atomicAdd(&g_ksum[qcol + c], ks4[c]);

    // block-reduce loss
    __syncthreads();
    float* red = reinterpret_cast<float*>(sh);
    red[tid] = loss_local;
    __syncthreads();
#pragma unroll
    for (int s = 128; s > 0; s >>= 1) {
        if (tid < s) red[tid] += red[tid + s];
        __syncthreads();
    }
    if (tid == 0) atomicAdd(&g_loss, red[0]);
}

__global__ void titans_final_kernel(const float* __restrict__ W,
                                    const float* __restrict__ gate_w,
                                    const float* __restrict__ gate_b,
                                    const float* __restrict__ S,
                                    float* __restrict__ out,
                                    int N) {
    __shared__ float gates_sh[3];
    __shared__ float red[256];
    __shared__ float scale_sh;
    const int tid = threadIdx.x;
    const float numel = (float)N * (float)D;

    const size_t loss_off = (size_t)N * D;
    const size_t nw_off   = loss_off + 1;
    const size_t ns_off   = nw_off + D * D;
    const size_t g_off    = ns_off + D * D;

    if (tid == 0) {
        float invN = 1.0f / (float)N;
        for (int i = 0; i < 3; i++) {
            float s = gate_b[i];
            for (int d = 0; d < D; d++) s += gate_w[i * D + d] * (g_ksum[d] * invN);
            gates_sh[i] = 1.0f / (1.0f + __expf(-s));
        }
        out[loss_off] = g_loss / numel;
    }
    __syncthreads();
    const float alpha = gates_sh[0];
    const float eta   = gates_sh[1];
    const float theta = gates_sh[2];

    float wlocal[16];
    float ss = 0.0f;
#pragma unroll
    for (int i = 0; i < 16; i++) {
        int idx = tid * 16 + i;
        float g = g_gradAcc[idx] * (2.0f / numel);
        g = fminf(1.0f, fmaxf(-1.0f, g));
        float ns = eta * S[idx] - 0.01f * theta * g;
        float nw = (1.0f - alpha) * W[idx] + ns;
        out[ns_off + idx] = ns;
        wlocal[i] = nw;
        ss += nw * nw;
    }
    red[tid] = ss;
    __syncthreads();
#pragma unroll
    for (int s = 128; s > 0; s >>= 1) {
        if (tid < s) red[tid] += red[tid + s];
        __syncthreads();
    }
    if (tid == 0) {
        float wnorm = sqrtf(red[0]);
        scale_sh = (wnorm > 10.0f) ? (10.0f / (wnorm + 1e-8f)) : 1.0f;
    }
    __syncthreads();
    const float sc = scale_sh;
#pragma unroll
    for (int i = 0; i < 16; i++) {
        int idx = tid * 16 + i;
        out[nw_off + idx] = wlocal[i] * sc;
    }
    if (tid < 3) out[g_off + tid] = gates_sh[tid];
}

extern "C" void kernel_launch(void* const* d_in, const int* in_sizes, int n_in,
                              void* d_out, int out_size) {
    const float* k  = (const float*)d_in[0];
    const float* v  = (const float*)d_in[1];
    const float* W  = (const float*)d_in[2];
    const float* gw = (const float*)d_in[3];
    const float* gb = (const float*)d_in[4];
    const float* S  = (const float*)d_in[5];
    float* out = (float*)d_out;

    const int N = in_sizes[0] / D;

    cudaFuncSetAttribute(titans_main_kernel,
                         cudaFuncAttributeMaxDynamicSharedMemorySize, SMEM_BYTES);

    zero_scratch_kernel<<<16, 256>>>();
    titans_main_kernel<<<296, 256, SMEM_BYTES>>>(k, v, W, out, N);
    titans_final_kernel<<<1, 256>>>(W, gw, gb, S, out, N);
}